// round 15
// baseline (speedup 1.0000x reference)
#include <cuda_runtime.h>
#include <cuda_fp16.h>
#include <cstdint>
#include <cstddef>

// Problem dims: y[b,m,n] = sum_k x[b,m,k] w[k,n]; flatten b,m -> M
#define MDIM 8192
#define KDIM 4096
#define NDIM 4096

// GEMM tiling: CTA 256x128x64, 8 warps (4m x 2n), warp tile 64x64, 3 stages,
// 1 CTA/SM, flat 8-unit pipeline per kt. Halved STS/MMA + barriers/MMA vs R14.
#define BM 256
#define BN 128
#define BK 64
#define STAGES 3
#define KT (KDIM / BK)  // 64
#define THREADS 256

#define LDA 72   // 64 + 8 pad (fp16 elems per A smem row)
#define LDB 136  // 128 + 8 pad
#define A_TILE_B (BM * LDA * 2)        // 36864
#define B_TILE_B (BK * LDB * 2)        // 17408
#define STAGE_B (A_TILE_B + B_TILE_B)  // 54272
#define SMEM_B (STAGES * STAGE_B)      // 162816 -> 1 CTA/SM

// fp16 scratch (allocation-free rule: __device__ globals)
__device__ __half g_xh[(size_t)MDIM * KDIM];  // 67 MB
__device__ __half g_wh[(size_t)KDIM * NDIM];  // 33.5 MB

static __device__ __forceinline__ uint32_t smem_u32(const void* p) {
    uint32_t a;
    asm("{ .reg .u64 t; cvta.to.shared.u64 t, %1; cvt.u32.u64 %0, t; }"
        : "=r"(a) : "l"(p));
    return a;
}

#define CP_ASYNC16(dst, src) \
    asm volatile("cp.async.cg.shared.global [%0], [%1], 16;" :: "r"(dst), "l"(src))
#define CP_COMMIT() asm volatile("cp.async.commit_group;" ::: "memory")
#define CP_WAIT(n)  asm volatile("cp.async.wait_group %0;" :: "n"(n) : "memory")

#define LDMATRIX_X4(r, addr)                                               \
    asm volatile("ldmatrix.sync.aligned.m8n8.x4.shared.b16 "               \
                 "{%0,%1,%2,%3}, [%4];"                                    \
                 : "=r"((r)[0]), "=r"((r)[1]), "=r"((r)[2]), "=r"((r)[3])  \
                 : "r"(addr))

#define LDMATRIX_X4_T(r, addr)                                             \
    asm volatile("ldmatrix.sync.aligned.m8n8.x4.trans.shared.b16 "         \
                 "{%0,%1,%2,%3}, [%4];"                                    \
                 : "=r"((r)[0]), "=r"((r)[1]), "=r"((r)[2]), "=r"((r)[3])  \
                 : "r"(addr))

#define MMA16816(d, a, b0, b1)                                             \
    asm volatile("mma.sync.aligned.m16n8k16.row.col.f32.f16.f16.f32 "      \
                 "{%0,%1,%2,%3}, {%4,%5,%6,%7}, {%8,%9}, {%0,%1,%2,%3};"   \
                 : "+f"((d)[0]), "+f"((d)[1]), "+f"((d)[2]), "+f"((d)[3])  \
                 : "r"((a)[0]), "r"((a)[1]), "r"((a)[2]), "r"((a)[3]),     \
                   "r"(b0), "r"(b1))

// ---------------------------------------------------------------------------
// prep: fused fp32 -> fp16 for both x and w (one launch)
// ---------------------------------------------------------------------------
#define XCHUNKS ((size_t)MDIM * KDIM / 4)  // 8388608 float4s
#define WCHUNKS ((size_t)KDIM * NDIM / 4)  // 4194304 float4s

__global__ void cvt_both_kernel(const float4* __restrict__ x4,
                                const float4* __restrict__ w4) {
    size_t i = (size_t)blockIdx.x * blockDim.x + threadIdx.x;
    const float4* src;
    uint2* dst;
    if (i < XCHUNKS) {
        src = x4 + i;
        dst = reinterpret_cast<uint2*>(g_xh) + i;
    } else {
        src = w4 + (i - XCHUNKS);
        dst = reinterpret_cast<uint2*>(g_wh) + (i - XCHUNKS);
    }
    float4 v = *src;
    __half2 h0 = __floats2half2_rn(v.x, v.y);
    __half2 h1 = __floats2half2_rn(v.z, v.w);
    uint2 o;
    o.x = *reinterpret_cast<uint32_t*>(&h0);
    o.y = *reinterpret_cast<uint32_t*>(&h1);
    *dst = o;
}

// ---------------------------------------------------------------------------
// GEMM
// ---------------------------------------------------------------------------
__global__ void __launch_bounds__(THREADS, 1) gemm_kernel(float* __restrict__ out) {
    extern __shared__ char smem_raw[];
    const uint32_t smem = smem_u32(smem_raw);

    const int tid = threadIdx.x;
    const int lane = tid & 31;
    const int wid = tid >> 5;
    const int warp_m = wid & 3;   // 0..3
    const int warp_n = wid >> 2;  // 0..1

    const int m0 = blockIdx.y * BM;
    const int n0 = blockIdx.x * BN;

    // ---- cp.async bases: A 2048 chunks (8/thread), B 1024 chunks (4/thread)
    const int rA = tid >> 3, chA = tid & 7;    // A rows 0..31 (+32*i), 8 ch/row
    const uint32_t sA0 = smem + (uint32_t)(rA * LDA + chA * 8) * 2;
    const __half* gA0 = g_xh + (size_t)(m0 + rA) * KDIM + chA * 8;
    const int rB = tid >> 4, chB = tid & 15;   // B rows 0..15 (+16*i), 16 ch/row
    const uint32_t sB0 = smem + A_TILE_B + (uint32_t)(rB * LDB + chB * 8) * 2;
    const __half* gB0 = g_wh + (size_t)rB * NDIM + n0 + chB * 8;

#define ISSUE_KT(slot, kt_)                                                  \
    do {                                                                     \
        const uint32_t sb = (uint32_t)(slot) * STAGE_B;                      \
        const size_t kb = (size_t)(kt_) * BK;                                \
        _Pragma("unroll")                                                    \
        for (int i = 0; i < 8; ++i)                                          \
            CP_ASYNC16(sA0 + sb + (uint32_t)(i * 32 * LDA * 2),              \
                       gA0 + (size_t)i * 32 * KDIM + kb);                    \
        _Pragma("unroll")                                                    \
        for (int i = 0; i < 4; ++i)                                          \
            CP_ASYNC16(sB0 + sb + (uint32_t)(i * 16 * LDB * 2),              \
                       gB0 + ((size_t)i * 16 + kb) * NDIM);                  \
    } while (0)

    // ---- fragment base addresses ----
    const uint32_t a_frag =
        smem + (uint32_t)((warp_m * 64 + (lane & 15)) * LDA + (lane >> 4) * 8) * 2;
    const uint32_t b_frag =
        smem + A_TILE_B +
        (uint32_t)((lane & 15) * LDB + warp_n * 64 + (lane >> 4) * 8) * 2;

    // fragment buffers: a_f[unit parity][j], b_f[kk parity][njblk(16n)]
    uint32_t a_f[2][2][4], b_f[2][4][4];

#define LOAD_A_HALF(ab, base, h, kk)                                         \
    do {                                                                     \
        _Pragma("unroll")                                                    \
        for (int j = 0; j < 2; ++j)                                          \
            LDMATRIX_X4(a_f[ab][j],                                          \
                        (base) + (uint32_t)((((h) * 2 + j) * 16) * LDA +     \
                                            (kk) * 16) * 2);                 \
    } while (0)

// load half (p = 0,1) of a kk's B fragments: njblk = 2p, 2p+1
#define LOAD_B_HALF(bb, base, kk, p)                                         \
    do {                                                                     \
        _Pragma("unroll")                                                    \
        for (int t = 0; t < 2; ++t)                                          \
            LDMATRIX_X4_T(b_f[bb][2 * (p) + t],                              \
                          (base) + (uint32_t)((kk) * 16 * LDB +              \
                                              (2 * (p) + t) * 16) * 2);      \
    } while (0)

    float acc[4][8][4];
#pragma unroll
    for (int mi = 0; mi < 4; ++mi)
#pragma unroll
        for (int ni = 0; ni < 8; ++ni)
#pragma unroll
            for (int q = 0; q < 4; ++q) acc[mi][ni][q] = 0.f;

    // ---- prologue: fill all 3 stages; slots 0,1 complete ----
    ISSUE_KT(0, 0); CP_COMMIT();
    ISSUE_KT(1, 1); CP_COMMIT();
    ISSUE_KT(2, 2); CP_COMMIT();
    CP_WAIT(1);
    __syncthreads();

    // preload unit 0 of kt 0
    LOAD_A_HALF(0, a_frag, 0, 0);
    LOAD_B_HALF(0, b_frag, 0, 0);
    LOAD_B_HALF(0, b_frag, 0, 1);

    // ---- mainloop ----
    for (int kt = 0; kt < KT; ++kt) {
        const uint32_t sb  = (uint32_t)(kt % 3) * STAGE_B;
        const uint32_t sbn = (uint32_t)((kt + 1) % 3) * STAGE_B;
        const uint32_t aB  = a_frag + sb,  bB  = b_frag + sb;
        const uint32_t aBn = a_frag + sbn, bBn = b_frag + sbn;

#pragma unroll
        for (int u = 0; u < 8; ++u) {
            const int kk = u >> 1, h = u & 1;
            // ---- prefetch fragments for unit u+1 ----
            if (u < 7) {
                const int un = u + 1;
                LOAD_A_HALF(un & 1, aB, un & 1, un >> 1);
            } else if (kt + 1 < KT) {
                LOAD_A_HALF(0, aBn, 0, 0);
            }
            // B(kk+1) spread over this kk's two units (cross-kt at kk==3)
            if (kk < 3) {
                LOAD_B_HALF((kk + 1) & 1, bB, kk + 1, h);
            } else if (kt + 1 < KT) {
                LOAD_B_HALF(0, bBn, 0, h);
            }
            // ---- 16 MMAs for unit u ----
#pragma unroll
            for (int j = 0; j < 2; ++j) {
                const int mi = h * 2 + j;
#pragma unroll
                for (int nb = 0; nb < 4; ++nb) {
                    MMA16816(acc[mi][2 * nb + 0], a_f[u & 1][j],
                             b_f[kk & 1][nb][0], b_f[kk & 1][nb][1]);
                    MMA16816(acc[mi][2 * nb + 1], a_f[u & 1][j],
                             b_f[kk & 1][nb][2], b_f[kk & 1][nb][3]);
                }
            }
        }

        // ---- stage rotation (invariant: slots kt+1, kt+2 ready) ----
        __syncthreads();                       // all warps done with slot kt
        if (kt + 3 < KT) ISSUE_KT(kt % 3, kt + 3);
        CP_COMMIT();
        CP_WAIT(1);                            // slot kt+2 complete
        __syncthreads();                       // ...and visible
    }

    // ---- epilogue: direct fp32 stores ----
    const int mg = m0 + warp_m * 64 + (lane >> 2);
    const int ng = n0 + warp_n * 64 + (lane & 3) * 2;
#pragma unroll
    for (int mi = 0; mi < 4; ++mi) {
#pragma unroll
        for (int ni = 0; ni < 8; ++ni) {
            float* p0 = out + (size_t)(mg + mi * 16) * NDIM + ng + ni * 8;
            float* p1 = p0 + 8 * NDIM;
            *reinterpret_cast<float2*>(p0) = make_float2(acc[mi][ni][0], acc[mi][ni][1]);
            *reinterpret_cast<float2*>(p1) = make_float2(acc[mi][ni][2], acc[mi][ni][3]);
        }
    }
}

// ---------------------------------------------------------------------------
extern "C" void kernel_launch(void* const* d_in, const int* in_sizes, int n_in,
                              void* d_out, int out_size) {
    const float* x = (const float*)d_in[0];  // (4, 2048, 4096) fp32
    const float* w = (const float*)d_in[1];  // (4096, 4096) fp32 ternary
    float* out = (float*)d_out;              // (4, 2048, 4096) fp32

    size_t total_chunks = XCHUNKS + WCHUNKS;  // 12582912
    cvt_both_kernel<<<(int)(total_chunks / 256), 256>>>(
        reinterpret_cast<const float4*>(x), reinterpret_cast<const float4*>(w));

    cudaFuncSetAttribute(gemm_kernel, cudaFuncAttributeMaxDynamicSharedMemorySize,
                         SMEM_B);
    dim3 grid(NDIM / BN, MDIM / BM);  // (32, 32)
    gemm_kernel<<<grid, THREADS, SMEM_B>>>(out);
}

// round 16
// speedup vs baseline: 1.1976x; 1.1976x over previous
#include <cuda_runtime.h>
#include <cuda_fp16.h>
#include <cstdint>
#include <cstddef>

// Problem dims: y[b,m,n] = sum_k x[b,m,k] w[k,n]; flatten b,m -> M
#define MDIM 8192
#define KDIM 4096
#define NDIM 4096

// GEMM tiling: CTA 128x128x64, 4 warps (2m x 2n), warp tile 64x64, 3 stages,
// 2 CTAs/SM. Flat 8-unit pipeline; cp.asyncs spread across units (no burst);
// single-barrier rotation {wait(1); sync}.
#define BM 128
#define BN 128
#define BK 64
#define STAGES 3
#define KT (KDIM / BK)  // 64
#define THREADS 128

#define LDA 72   // 64 + 8 pad (fp16 elems per A smem row)
#define LDB 136  // 128 + 8 pad
#define A_TILE_B (BM * LDA * 2)        // 18432
#define B_TILE_B (BK * LDB * 2)        // 17408
#define STAGE_B (A_TILE_B + B_TILE_B)  // 35840
#define SMEM_B (STAGES * STAGE_B)      // 107520 -> 2 CTAs/SM

// fp16 scratch (allocation-free rule: __device__ globals)
__device__ __half g_xh[(size_t)MDIM * KDIM];  // 67 MB
__device__ __half g_wh[(size_t)KDIM * NDIM];  // 33.5 MB

static __device__ __forceinline__ uint32_t smem_u32(const void* p) {
    uint32_t a;
    asm("{ .reg .u64 t; cvta.to.shared.u64 t, %1; cvt.u32.u64 %0, t; }"
        : "=r"(a) : "l"(p));
    return a;
}

#define CP_ASYNC16(dst, src) \
    asm volatile("cp.async.cg.shared.global [%0], [%1], 16;" :: "r"(dst), "l"(src))
#define CP_COMMIT() asm volatile("cp.async.commit_group;" ::: "memory")
#define CP_WAIT(n)  asm volatile("cp.async.wait_group %0;" :: "n"(n) : "memory")

#define LDMATRIX_X4(r, addr)                                               \
    asm volatile("ldmatrix.sync.aligned.m8n8.x4.shared.b16 "               \
                 "{%0,%1,%2,%3}, [%4];"                                    \
                 : "=r"((r)[0]), "=r"((r)[1]), "=r"((r)[2]), "=r"((r)[3])  \
                 : "r"(addr))

#define LDMATRIX_X4_T(r, addr)                                             \
    asm volatile("ldmatrix.sync.aligned.m8n8.x4.trans.shared.b16 "         \
                 "{%0,%1,%2,%3}, [%4];"                                    \
                 : "=r"((r)[0]), "=r"((r)[1]), "=r"((r)[2]), "=r"((r)[3])  \
                 : "r"(addr))

#define MMA16816(d, a, b0, b1)                                             \
    asm volatile("mma.sync.aligned.m16n8k16.row.col.f32.f16.f16.f32 "      \
                 "{%0,%1,%2,%3}, {%4,%5,%6,%7}, {%8,%9}, {%0,%1,%2,%3};"   \
                 : "+f"((d)[0]), "+f"((d)[1]), "+f"((d)[2]), "+f"((d)[3])  \
                 : "r"((a)[0]), "r"((a)[1]), "r"((a)[2]), "r"((a)[3]),     \
                   "r"(b0), "r"(b1))

// ---------------------------------------------------------------------------
// prep: fused fp32 -> fp16 for both x and w (one launch)
// ---------------------------------------------------------------------------
#define XCHUNKS ((size_t)MDIM * KDIM / 4)  // 8388608 float4s
#define WCHUNKS ((size_t)KDIM * NDIM / 4)  // 4194304 float4s

__global__ void cvt_both_kernel(const float4* __restrict__ x4,
                                const float4* __restrict__ w4) {
    size_t i = (size_t)blockIdx.x * blockDim.x + threadIdx.x;
    const float4* src;
    uint2* dst;
    if (i < XCHUNKS) {
        src = x4 + i;
        dst = reinterpret_cast<uint2*>(g_xh) + i;
    } else {
        src = w4 + (i - XCHUNKS);
        dst = reinterpret_cast<uint2*>(g_wh) + (i - XCHUNKS);
    }
    float4 v = *src;
    __half2 h0 = __floats2half2_rn(v.x, v.y);
    __half2 h1 = __floats2half2_rn(v.z, v.w);
    uint2 o;
    o.x = *reinterpret_cast<uint32_t*>(&h0);
    o.y = *reinterpret_cast<uint32_t*>(&h1);
    *dst = o;
}

// ---------------------------------------------------------------------------
// GEMM
// ---------------------------------------------------------------------------
__global__ void __launch_bounds__(THREADS, 2) gemm_kernel(float* __restrict__ out) {
    extern __shared__ char smem_raw[];
    const uint32_t smem = smem_u32(smem_raw);

    const int tid = threadIdx.x;
    const int lane = tid & 31;
    const int wid = tid >> 5;
    const int warp_m = wid & 1;   // 0..1
    const int warp_n = wid >> 1;  // 0..1

    const int m0 = blockIdx.y * BM;
    const int n0 = blockIdx.x * BN;

    // ---- cp.async bases: A 1024 chunks (8/thread), B 1024 chunks (8/thread)
    const int rA = tid >> 3, chA = tid & 7;    // A rows 0..15 (+16*i)
    const uint32_t sA0 = smem + (uint32_t)(rA * LDA + chA * 8) * 2;
    const __half* gA0 = g_xh + (size_t)(m0 + rA) * KDIM + chA * 8;
    const int rB = tid >> 4, chB = tid & 15;   // B rows 0..7 (+8*i)
    const uint32_t sB0 = smem + A_TILE_B + (uint32_t)(rB * LDB + chB * 8) * 2;
    const __half* gB0 = g_wh + (size_t)rB * NDIM + n0 + chB * 8;

// quarter-issues: q selects 4 of the 8 per-matrix chunks (i = 4q..4q+3)
#define ISSUE_A_QUARTER(slot, kt_, q)                                        \
    do {                                                                     \
        const uint32_t sb_ = (uint32_t)(slot) * STAGE_B;                     \
        const size_t kb_ = (size_t)(kt_) * BK;                               \
        _Pragma("unroll")                                                    \
        for (int i = 4 * (q); i < 4 * (q) + 4; ++i)                          \
            CP_ASYNC16(sA0 + sb_ + (uint32_t)(i * 16 * LDA * 2),             \
                       gA0 + (size_t)i * 16 * KDIM + kb_);                   \
    } while (0)
#define ISSUE_B_QUARTER(slot, kt_, q)                                        \
    do {                                                                     \
        const uint32_t sb_ = (uint32_t)(slot) * STAGE_B;                     \
        const size_t kb_ = (size_t)(kt_) * BK;                               \
        _Pragma("unroll")                                                    \
        for (int i = 4 * (q); i < 4 * (q) + 4; ++i)                          \
            CP_ASYNC16(sB0 + sb_ + (uint32_t)(i * 8 * LDB * 2),              \
                       gB0 + ((size_t)i * 8 + kb_) * NDIM);                  \
    } while (0)
#define ISSUE_KT_FULL(slot, kt_)                                             \
    do {                                                                     \
        ISSUE_A_QUARTER(slot, kt_, 0); ISSUE_A_QUARTER(slot, kt_, 1);        \
        ISSUE_B_QUARTER(slot, kt_, 0); ISSUE_B_QUARTER(slot, kt_, 1);        \
    } while (0)

    // ---- fragment base addresses ----
    const uint32_t a_frag =
        smem + (uint32_t)((warp_m * 64 + (lane & 15)) * LDA + (lane >> 4) * 8) * 2;
    const uint32_t b_frag =
        smem + A_TILE_B +
        (uint32_t)((lane & 15) * LDB + warp_n * 64 + (lane >> 4) * 8) * 2;

    // fragment buffers: a_f[unit parity][j], b_f[kk parity][njblk(16n)]
    uint32_t a_f[2][2][4], b_f[2][4][4];

#define LOAD_A_HALF(ab, base, h, kk)                                         \
    do {                                                                     \
        _Pragma("unroll")                                                    \
        for (int j = 0; j < 2; ++j)                                          \
            LDMATRIX_X4(a_f[ab][j],                                          \
                        (base) + (uint32_t)((((h) * 2 + j) * 16) * LDA +     \
                                            (kk) * 16) * 2);                 \
    } while (0)

#define LOAD_B_HALF(bb, base, kk, p)                                         \
    do {                                                                     \
        _Pragma("unroll")                                                    \
        for (int t = 0; t < 2; ++t)                                          \
            LDMATRIX_X4_T(b_f[bb][2 * (p) + t],                              \
                          (base) + (uint32_t)((kk) * 16 * LDB +              \
                                              (2 * (p) + t) * 16) * 2);      \
    } while (0)

    float acc[4][8][4];
#pragma unroll
    for (int mi = 0; mi < 4; ++mi)
#pragma unroll
        for (int ni = 0; ni < 8; ++ni)
#pragma unroll
            for (int q = 0; q < 4; ++q) acc[mi][ni][q] = 0.f;

    // ---- prologue: groups 0,1 resident & visible ----
    ISSUE_KT_FULL(0, 0); CP_COMMIT();
    ISSUE_KT_FULL(1, 1); CP_COMMIT();
    CP_WAIT(0);
    __syncthreads();

    // ---- mainloop ----
    // Invariant at top of iter kt: slot kt%3 and slot (kt+1)%3 complete+visible
    // (kt+1 guaranteed by prior rotation's wait(1) since newest commit = kt+2).
    for (int kt = 0; kt < KT; ++kt) {
        const uint32_t sb = (uint32_t)(kt % 3) * STAGE_B;
        const uint32_t aB = a_frag + sb, bB = b_frag + sb;
        const int s2 = (kt + 2) % 3;
        const bool more = (kt + 2) < KT;

        // preload unit 0 fragments (slot kt complete+visible per invariant)
        LOAD_A_HALF(0, aB, 0, 0);
        LOAD_B_HALF(0, bB, 0, 0);
        LOAD_B_HALF(0, bB, 0, 1);

#pragma unroll
        for (int u = 0; u < 8; ++u) {
            const int kk = u >> 1, h = u & 1;
            // ---- spread-issue group kt+2 over units 0..3 ----
            if (u == 0 && more) ISSUE_A_QUARTER(s2, kt + 2, 0);
            if (u == 1 && more) ISSUE_A_QUARTER(s2, kt + 2, 1);
            if (u == 2 && more) ISSUE_B_QUARTER(s2, kt + 2, 0);
            if (u == 3) {
                if (more) ISSUE_B_QUARTER(s2, kt + 2, 1);
                CP_COMMIT();   // group kt+2 committed (empty group ok at tail)
            }
            // ---- prefetch fragments for unit u+1 (within this kt) ----
            if (u < 7) {
                const int un = u + 1;
                LOAD_A_HALF(un & 1, aB, un & 1, un >> 1);
            }
            if (kk < 3) LOAD_B_HALF((kk + 1) & 1, bB, kk + 1, h);
            // ---- 16 MMAs for unit u ----
#pragma unroll
            for (int j = 0; j < 2; ++j) {
                const int mi = h * 2 + j;
#pragma unroll
                for (int nb = 0; nb < 4; ++nb) {
                    MMA16816(acc[mi][2 * nb + 0], a_f[u & 1][j],
                             b_f[kk & 1][nb][0], b_f[kk & 1][nb][1]);
                    MMA16816(acc[mi][2 * nb + 1], a_f[u & 1][j],
                             b_f[kk & 1][nb][2], b_f[kk & 1][nb][3]);
                }
            }
        }

        // ---- rotation: single barrier ----
        CP_WAIT(1);        // newest committed = kt+2 -> kt+1 complete
        __syncthreads();   // visibility of kt+1; all threads done with slot kt
    }

    // ---- epilogue: direct fp32 stores ----
    const int mg = m0 + warp_m * 64 + (lane >> 2);
    const int ng = n0 + warp_n * 64 + (lane & 3) * 2;
#pragma unroll
    for (int mi = 0; mi < 4; ++mi) {
#pragma unroll
        for (int ni = 0; ni < 8; ++ni) {
            float* p0 = out + (size_t)(mg + mi * 16) * NDIM + ng + ni * 8;
            float* p1 = p0 + 8 * NDIM;
            *reinterpret_cast<float2*>(p0) = make_float2(acc[mi][ni][0], acc[mi][ni][1]);
            *reinterpret_cast<float2*>(p1) = make_float2(acc[mi][ni][2], acc[mi][ni][3]);
        }
    }
}

// ---------------------------------------------------------------------------
extern "C" void kernel_launch(void* const* d_in, const int* in_sizes, int n_in,
                              void* d_out, int out_size) {
    const float* x = (const float*)d_in[0];  // (4, 2048, 4096) fp32
    const float* w = (const float*)d_in[1];  // (4096, 4096) fp32 ternary
    float* out = (float*)d_out;              // (4, 2048, 4096) fp32

    size_t total_chunks = XCHUNKS + WCHUNKS;  // 12582912
    cvt_both_kernel<<<(int)(total_chunks / 256), 256>>>(
        reinterpret_cast<const float4*>(x), reinterpret_cast<const float4*>(w));

    cudaFuncSetAttribute(gemm_kernel, cudaFuncAttributeMaxDynamicSharedMemorySize,
                         SMEM_B);
    dim3 grid(NDIM / BN, MDIM / BM);  // (32, 64)
    gemm_kernel<<<grid, THREADS, SMEM_B>>>(out);
}